// round 9
// baseline (speedup 1.0000x reference)
#include <cuda_runtime.h>

#define BQ 2
#define NPTS 512
#define INDIM 512
#define MEMD 300
#define HIDD 64
#define NEG 0.01f
#define NN (NPTS*NPTS)

typedef unsigned long long ull;

// ---------------- scratch ----------------
__device__ float g_h[1024*MEMD];
__device__ float g_s[1024*128];
__device__ float g_u[BQ*NN];
__device__ float g_f[1024*MEMD];
__device__ float g_sum[4];     // [layer][batch]

// ---------------- f32x2 helpers ----------------
__device__ __forceinline__ ull dup2(float x) {
    ull r; asm("mov.b64 %0, {%1,%1};" : "=l"(r) : "f"(x)); return r;
}
__device__ __forceinline__ void ffma2(ull& d, ull a, ull b) {
    asm("fma.rn.f32x2 %0, %1, %2, %0;" : "+l"(d) : "l"(a), "l"(b));
}
__device__ __forceinline__ float2 unpk(ull v) {
    float2 r; asm("mov.b64 {%0,%1}, %2;" : "=f"(r.x), "=f"(r.y) : "l"(v)); return r;
}

// ====== GEMM core: 16x64 tile, 128 thr, 2x4 micro, f32x2, reg-staged prefetch ======
// C[cr0..+16, cc0..+64] = scale * A[ar0..+16, :K] @ B[:K, bc0..+64] + bias
__device__ __forceinline__ void gemm16(
    const float* __restrict__ A, int lda, int ar0, int K,
    const float* __restrict__ B, int ldb, int bc0, int bcmax,
    float* __restrict__ C, int ldc, int cr0, int cc0, int ccmax,
    const float* __restrict__ bias, float scale)
{
    __shared__ __align__(16) float As[16*20];   // [k][row], stride 20
    __shared__ __align__(16) float Bs[16*68];   // [k][col], stride 68
    int tid = threadIdx.x;
    int tx = tid & 15, ty = tid >> 4;           // tx: col-quad, ty: row-pair
    int ty2 = ty*2, tx4 = tx*4;
    int kA = tid & 15, rA = tid >> 4;           // A stage coords (2/thread)
    int cB = tid & 63, kB = tid >> 6;           // B stage coords (8/thread)
    int bc = bc0 + cB;
    bool bok = bc < bcmax;
    ull acc[2][2] = {};
    float ra[2], rb[8];
    // prefetch chunk 0
    #pragma unroll
    for (int p = 0; p < 2; p++)
        ra[p] = (kA < K) ? A[(size_t)(ar0 + rA + 8*p)*lda + kA] : 0.f;
    #pragma unroll
    for (int p = 0; p < 8; p++) {
        int bk = kB + 2*p;
        rb[p] = (bk < K && bok) ? B[(size_t)bk*ldb + bc] : 0.f;
    }
    for (int k0 = 0; k0 < K; k0 += 16) {
        #pragma unroll
        for (int p = 0; p < 2; p++) As[kA*20 + rA + 8*p] = ra[p];
        #pragma unroll
        for (int p = 0; p < 8; p++) Bs[(kB + 2*p)*68 + cB] = rb[p];
        __syncthreads();
        int kn = k0 + 16;
        if (kn < K) {                            // prefetch next chunk during compute
            #pragma unroll
            for (int p = 0; p < 2; p++) {
                int ac = kn + kA;
                ra[p] = (ac < K) ? A[(size_t)(ar0 + rA + 8*p)*lda + ac] : 0.f;
            }
            #pragma unroll
            for (int p = 0; p < 8; p++) {
                int bk = kn + kB + 2*p;
                rb[p] = (bk < K && bok) ? B[(size_t)bk*ldb + bc] : 0.f;
            }
        }
        #pragma unroll
        for (int k = 0; k < 16; k++) {
            float2 av = *(const float2*)&As[k*20 + ty2];
            ulonglong2 bv = *(const ulonglong2*)&Bs[k*68 + tx4];
            ull a0 = dup2(av.x), a1 = dup2(av.y);
            ffma2(acc[0][0], a0, bv.x); ffma2(acc[0][1], a0, bv.y);
            ffma2(acc[1][0], a1, bv.x); ffma2(acc[1][1], a1, bv.y);
        }
        __syncthreads();
    }
    int cc = cc0 + tx4;
    if (cc < ccmax) {
        float4 bb = bias ? *(const float4*)&bias[cc] : make_float4(0.f,0.f,0.f,0.f);
        #pragma unroll
        for (int r = 0; r < 2; r++) {
            float2 lo = unpk(acc[r][0]), hi = unpk(acc[r][1]);
            float4 v = make_float4(lo.x*scale + bb.x, lo.y*scale + bb.y,
                                   hi.x*scale + bb.z, hi.y*scale + bb.w);
            *(float4*)&C[(size_t)(cr0 + ty2 + r)*ldc + cc] = v;
        }
    }
}

// ============ h = A @ W + bias  (grid 5 x 64 -> 320 CTAs) ============
__global__ void __launch_bounds__(128) k_h(
    const float* __restrict__ Aext, int use_gf,
    const float* __restrict__ W, const float* __restrict__ bias,
    int K, int lay)
{
    if (blockIdx.x == 0 && blockIdx.y == 0 && threadIdx.x < 2)
        g_sum[lay*2 + threadIdx.x] = 0.f;
    const float* A = use_gf ? g_f : Aext;
    gemm16(A, K, blockIdx.y*16, K,
           W, MEMD, blockIdx.x*64, MEMD,
           g_h, MEMD, blockIdx.y*16, blockIdx.x*64, MEMD, bias, 1.f);
}

// ============ s = h @ [a1w_top | a1w_bot] (+a1b)  (grid 2 x 64 -> 128 CTAs) ============
__global__ void __launch_bounds__(128) k_s(
    const float* __restrict__ a1w, const float* __restrict__ a1b)
{
    int ct = blockIdx.x;
    gemm16(g_h, MEMD, blockIdx.y*16, MEMD,
           a1w + ct*MEMD*HIDD, HIDD, 0, HIDD,
           g_s, 128, blockIdx.y*16, ct*64, 128,
           ct == 0 ? a1b : (const float*)0, 1.f);
}

// ===== u = exp(masked leaky(e)) + batch sum  (64i x 32j tiles, 128 thr, 256 CTAs) =====
__global__ void __launch_bounds__(128) k_e(
    const float* __restrict__ adj, const float* __restrict__ a2w,
    const float* __restrict__ a2b, int lay)
{
    __shared__ __align__(16) float Si[64*68];    // [h][i_local 0..63]
    __shared__ __align__(16) float Sj[64*36];    // [h][j_local 0..31]
    __shared__ float Wv[64];
    __shared__ float red[128];
    int tid = threadIdx.x;
    int tx = tid & 7, ty = tid >> 3;             // tx: j-quad(8), ty: i-quad(16)
    int b = blockIdx.z;
    int i0 = blockIdx.y * 64, j0 = blockIdx.x * 32;
    if (tid < 64) Wv[tid] = a2w[tid];
    {
        int i = tid & 63, hb = tid >> 6;         // Si: 32 elems/thread
        #pragma unroll
        for (int p = 0; p < 32; p++) {
            int h = hb + 2*p;
            Si[h*68 + i] = g_s[(size_t)(b*NPTS + i0 + i)*128 + h];
        }
        int j = tid & 31, hb2 = tid >> 5;        // Sj: 16 elems/thread
        #pragma unroll
        for (int p = 0; p < 16; p++) {
            int h = hb2 + 4*p;
            Sj[h*36 + j] = g_s[(size_t)(b*NPTS + j0 + j)*128 + 64 + h];
        }
    }
    __syncthreads();
    float acc[4][4] = {};
    int i_l = ty*4, j_l = tx*4;
    #pragma unroll 4
    for (int h = 0; h < 64; h++) {
        float w = Wv[h];
        float4 si = *(const float4*)&Si[h*68 + i_l];
        float4 sj = *(const float4*)&Sj[h*36 + j_l];
        float siv[4] = {si.x, si.y, si.z, si.w};
        float sjv[4] = {sj.x, sj.y, sj.z, sj.w};
        #pragma unroll
        for (int di = 0; di < 4; di++)
            #pragma unroll
            for (int dj = 0; dj < 4; dj++)
                acc[di][dj] = fmaf(fmaxf(siv[di] + sjv[dj], 0.f), w, acc[di][dj]);
    }
    float ab = a2b[0];
    float lsum = 0.f;
    #pragma unroll
    for (int di = 0; di < 4; di++) {
        int i = i0 + i_l + di;
        float4 av = *(const float4*)&adj[(size_t)(b*NPTS + i)*NPTS + j0 + j_l];
        float am[4] = {av.x, av.y, av.z, av.w};
        float o[4];
        #pragma unroll
        for (int dj = 0; dj < 4; dj++) {
            float e = acc[di][dj] + ab;
            e = (e > 0.f) ? e : NEG * e;
            float lg = e * am[dj] + (1.f - am[dj]) * (-1e30f);
            o[dj] = __expf(lg);                  // masked -> exactly 0
        }
        *(float4*)&g_u[(size_t)b*NN + i*NPTS + j0 + j_l] =
            make_float4(o[0], o[1], o[2], o[3]);
        lsum += (o[0] + o[1]) + (o[2] + o[3]);
    }
    red[tid] = lsum;
    __syncthreads();
    for (int s = 64; s > 0; s >>= 1) {
        if (tid < s) red[tid] += red[tid + s];
        __syncthreads();
    }
    if (tid == 0) atomicAdd(&g_sum[lay*2 + b], red[0]);
}

// ============ out = (U @ h) * (1/sum)  (grid 5 x 32 x 2 -> 320 CTAs) ============
__global__ void __launch_bounds__(128) k_out(float* __restrict__ out, int to_gf, int lay)
{
    int b = blockIdx.z;
    float inv = 1.f / g_sum[lay*2 + b];
    float* dst = (to_gf ? g_f : out) + (size_t)b*NPTS*MEMD;
    gemm16(g_u + (size_t)b*NN, NPTS, blockIdx.y*16, NPTS,
           g_h + (size_t)b*NPTS*MEMD, MEMD, blockIdx.x*64, MEMD,
           dst, MEMD, blockIdx.y*16, blockIdx.x*64, MEMD,
           (const float*)0, inv);
}

// ---------------- host ----------------
extern "C" void kernel_launch(void* const* d_in, const int* in_sizes, int n_in,
                              void* d_out, int out_size) {
    const float* feature = (const float*)d_in[0];
    const float* adj     = (const float*)d_in[1];
    const float* w0      = (const float*)d_in[2];
    const float* b0      = (const float*)d_in[3];
    const float* w1      = (const float*)d_in[4];
    const float* b1      = (const float*)d_in[5];
    const float* a1w     = (const float*)d_in[6];
    const float* a1b     = (const float*)d_in[7];
    const float* a2w     = (const float*)d_in[8];
    const float* a2b     = (const float*)d_in[9];
    float* out = (float*)d_out;

    dim3 gh(5, 64);          // 320 CTAs
    dim3 gs(2, 64);          // 128 CTAs
    dim3 ge(16, 8, BQ);      // 512/32 x 512/64 x 2 -> 256 CTAs
    dim3 go(5, 32, BQ);      // 320 CTAs

    // ---- layer 0 ----
    k_h  <<<gh, 128>>>(feature, 0, w0, b0, INDIM, 0);
    k_s  <<<gs, 128>>>(a1w, a1b);
    k_e  <<<ge, 128>>>(adj, a2w, a2b, 0);
    k_out<<<go, 128>>>(out, 1, 0);               // -> g_f

    // ---- layer 1 ----
    k_h  <<<gh, 128>>>(nullptr, 1, w1, b1, MEMD, 1);
    k_s  <<<gs, 128>>>(a1w, a1b);
    k_e  <<<ge, 128>>>(adj, a2w, a2b, 1);
    k_out<<<go, 128>>>(out, 0, 1);               // -> d_out
}